// round 1
// baseline (speedup 1.0000x reference)
#include <cuda_runtime.h>

#define T_  3
#define H_  96
#define W_  96
#define C_  128
#define CK  128
#define NHEAD 8
#define DH  16
#define NT  (T_*H_*W_)      // 27648
#define P_  25
#define TP  75              // T_*P_
#define KPAD 132            // padded SMEM row stride for K/V tiles

__device__ float g_Q[NT*CK];
__device__ float g_K[NT*CK];
__device__ float g_V[NT*CK];
__device__ float g_O[NT*CK];

// ---------------------------------------------------------------------------
// Kernel 1: fused QKV projection + embedding adds.
// Grid: (NT/64, 3). Block: 256 threads. Each block: 64 tokens x 128 outputs.
// ---------------------------------------------------------------------------
__global__ __launch_bounds__(256) void qkv_kernel(
    const float* __restrict__ x,
    const float* __restrict__ Wq,
    const float* __restrict__ Wk,
    const float* __restrict__ Wv,
    const float* __restrict__ temp_emb,
    const float* __restrict__ sp_emb)
{
    __shared__ float xs[64][32];
    __shared__ float ws[32][128];

    const int which = blockIdx.y;       // 0=Q, 1=K, 2=V
    const float* Wm = (which == 0) ? Wq : (which == 1) ? Wk : Wv;
    float* dst      = (which == 0) ? g_Q : (which == 1) ? g_K : g_V;

    const int m0  = blockIdx.x * 64;
    const int tid = threadIdx.x;
    const int tx  = tid & 15;           // 16 col-groups of 8
    const int ty  = tid >> 4;           // 16 row-groups of 4

    float acc[4][8];
#pragma unroll
    for (int i = 0; i < 4; i++)
#pragma unroll
        for (int j = 0; j < 8; j++) acc[i][j] = 0.f;

    for (int k0 = 0; k0 < 128; k0 += 32) {
        // x tile: 64x32 floats = 512 float4, 2 per thread
        {
            int idx = tid;
#pragma unroll
            for (int it = 0; it < 2; it++) {
                int m = idx >> 3, k4 = idx & 7;
                float4 v = *(const float4*)&x[(size_t)(m0 + m) * 128 + k0 + k4 * 4];
                *(float4*)&xs[m][k4 * 4] = v;
                idx += 256;
            }
        }
        // W tile: 32x128 floats = 1024 float4, 4 per thread
        {
            int idx = tid;
#pragma unroll
            for (int it = 0; it < 4; it++) {
                int k = idx >> 5, c4 = idx & 31;
                float4 v = *(const float4*)&Wm[(size_t)(k0 + k) * 128 + c4 * 4];
                *(float4*)&ws[k][c4 * 4] = v;
                idx += 256;
            }
        }
        __syncthreads();
#pragma unroll
        for (int kk = 0; kk < 32; kk++) {
            float a[4], b[8];
#pragma unroll
            for (int i = 0; i < 4; i++) a[i] = xs[ty * 4 + i][kk];
            float4 b0 = *(float4*)&ws[kk][tx * 8];
            float4 b1 = *(float4*)&ws[kk][tx * 8 + 4];
            b[0] = b0.x; b[1] = b0.y; b[2] = b0.z; b[3] = b0.w;
            b[4] = b1.x; b[5] = b1.y; b[6] = b1.z; b[7] = b1.w;
#pragma unroll
            for (int i = 0; i < 4; i++)
#pragma unroll
                for (int j = 0; j < 8; j++) acc[i][j] += a[i] * b[j];
        }
        __syncthreads();
    }

    // epilogue: embedding adds + store
#pragma unroll
    for (int i = 0; i < 4; i++) {
        const int n   = m0 + ty * 4 + i;
        const int t   = n / (H_ * W_);
        const int rem = n % (H_ * W_);
        const int y   = rem / W_;
        const int xq  = rem % W_;
        const int col0 = tx * 8;

        if (which <= 1) {   // Q and K get temp_emb
#pragma unroll
            for (int j = 0; j < 8; j++)
                acc[i][j] += temp_emb[t * CK + col0 + j];
        }
        if (which == 0) {   // Q gets sp_emb[qidx]
            const int yc = min(max(y, 2), H_ - 3);
            const int xc = min(max(xq, 2), W_ - 3);
            const int qidx = (y - yc + 2) * 5 + (xq - xc + 2);
#pragma unroll
            for (int j = 0; j < 8; j++)
                acc[i][j] += sp_emb[qidx * CK + col0 + j];
        }
        *(float4*)&dst[(size_t)n * CK + col0]     = make_float4(acc[i][0], acc[i][1], acc[i][2], acc[i][3]);
        *(float4*)&dst[(size_t)n * CK + col0 + 4] = make_float4(acc[i][4], acc[i][5], acc[i][6], acc[i][7]);
    }
}

// ---------------------------------------------------------------------------
// Kernel 2: attention. One block per (y, x). 24 warps = 3 frames x 8 heads.
// Gathers 75 K/V rows (5x5 neighborhood x 3 frames) into SMEM, warp-level
// softmax over 75 keys, writes O = attn @ V.
// ---------------------------------------------------------------------------
__global__ __launch_bounds__(768) void attn_kernel(const float* __restrict__ sp_emb)
{
    extern __shared__ float sm[];
    float* Ksm = sm;                       // TP x KPAD
    float* Vsm = Ksm + TP * KPAD;          // TP x KPAD
    float* Qsm = Vsm + TP * KPAD;          // T_ x CK
    float* Asm = Qsm + T_ * CK;            // 24 x 76 (exp weights)

    const int y   = blockIdx.y;
    const int xq  = blockIdx.x;
    const int tid = threadIdx.x;
    const int yc = min(max(y, 2), H_ - 3);
    const int xc = min(max(xq, 2), W_ - 3);

    // Load Q (embeddings already folded in by qkv_kernel)
    for (int i = tid; i < T_ * CK; i += 768) {
        int t = i >> 7, c = i & 127;
        Qsm[i] = g_Q[(size_t)(t * H_ * W_ + y * W_ + xq) * CK + c];
    }
    // Gather K (+sp_emb) and V: 75 rows x 32 float4 each
    for (int i = tid; i < TP * 32; i += 768) {
        int j  = i >> 5;
        int c4 = (i & 31) * 4;
        int t  = j / 25, p = j % 25;
        int py = p / 5,  px = p % 5;
        int n  = t * H_ * W_ + (yc - 2 + py) * W_ + (xc - 2 + px);
        float4 kv = *(const float4*)&g_K[(size_t)n * CK + c4];
        float4 sp = *(const float4*)&sp_emb[p * CK + c4];
        kv.x += sp.x; kv.y += sp.y; kv.z += sp.z; kv.w += sp.w;
        *(float4*)&Ksm[j * KPAD + c4] = kv;
        *(float4*)&Vsm[j * KPAD + c4] = *(const float4*)&g_V[(size_t)n * CK + c4];
    }
    __syncthreads();

    const int w    = tid >> 5;
    const int lane = tid & 31;
    const int t    = w / NHEAD;
    const int h    = w % NHEAD;

    float q[DH];
#pragma unroll
    for (int d = 0; d < DH; d++) q[d] = Qsm[t * CK + h * DH + d];

    // scores: lane handles keys {lane, lane+32, lane+64}
    float sc[3];
    float mloc = -1e30f;
#pragma unroll
    for (int r = 0; r < 3; r++) {
        int j = lane + r * 32;
        float s = -1e30f;
        if (j < TP) {
            const float* kr = &Ksm[j * KPAD + h * DH];
            s = 0.f;
#pragma unroll
            for (int d = 0; d < DH; d++) s += q[d] * kr[d];
            s *= 0.25f;   // 1/sqrt(16)
        }
        sc[r] = s;
        mloc = fmaxf(mloc, s);
    }
#pragma unroll
    for (int o = 16; o; o >>= 1)
        mloc = fmaxf(mloc, __shfl_xor_sync(0xffffffffu, mloc, o));

    float ssum = 0.f;
#pragma unroll
    for (int r = 0; r < 3; r++) {
        int j = lane + r * 32;
        if (j < TP) {
            float ev = __expf(sc[r] - mloc);
            ssum += ev;
            Asm[w * 76 + j] = ev;
        }
    }
#pragma unroll
    for (int o = 16; o; o >>= 1)
        ssum += __shfl_xor_sync(0xffffffffu, ssum, o);
    __syncwarp();

    // AV: lane = d + 16*half; each half accumulates ~38 keys
    const int d    = lane & 15;
    const int half = lane >> 4;
    const int j0 = half ? 38 : 0;
    const int j1 = half ? TP : 38;
    float acc = 0.f;
    for (int j = j0; j < j1; j++)
        acc += Asm[w * 76 + j] * Vsm[j * KPAD + h * DH + d];
    acc += __shfl_xor_sync(0xffffffffu, acc, 16);

    if (half == 0) {
        int n = t * H_ * W_ + y * W_ + xq;
        g_O[(size_t)n * CK + h * DH + d] = acc / ssum;
    }
}

// ---------------------------------------------------------------------------
// Kernel 3: output projection O @ Wo with transposed writeout
// out[(y*W + x)*T*C + t*C + c]
// ---------------------------------------------------------------------------
__global__ __launch_bounds__(256) void outproj_kernel(
    const float* __restrict__ Wo, float* __restrict__ out)
{
    __shared__ float xs[64][32];
    __shared__ float ws[32][128];

    const int m0  = blockIdx.x * 64;
    const int tid = threadIdx.x;
    const int tx  = tid & 15;
    const int ty  = tid >> 4;

    float acc[4][8];
#pragma unroll
    for (int i = 0; i < 4; i++)
#pragma unroll
        for (int j = 0; j < 8; j++) acc[i][j] = 0.f;

    for (int k0 = 0; k0 < 128; k0 += 32) {
        {
            int idx = tid;
#pragma unroll
            for (int it = 0; it < 2; it++) {
                int m = idx >> 3, k4 = idx & 7;
                float4 v = *(const float4*)&g_O[(size_t)(m0 + m) * 128 + k0 + k4 * 4];
                *(float4*)&xs[m][k4 * 4] = v;
                idx += 256;
            }
        }
        {
            int idx = tid;
#pragma unroll
            for (int it = 0; it < 4; it++) {
                int k = idx >> 5, c4 = idx & 31;
                float4 v = *(const float4*)&Wo[(size_t)(k0 + k) * 128 + c4 * 4];
                *(float4*)&ws[k][c4 * 4] = v;
                idx += 256;
            }
        }
        __syncthreads();
#pragma unroll
        for (int kk = 0; kk < 32; kk++) {
            float a[4], b[8];
#pragma unroll
            for (int i = 0; i < 4; i++) a[i] = xs[ty * 4 + i][kk];
            float4 b0 = *(float4*)&ws[kk][tx * 8];
            float4 b1 = *(float4*)&ws[kk][tx * 8 + 4];
            b[0] = b0.x; b[1] = b0.y; b[2] = b0.z; b[3] = b0.w;
            b[4] = b1.x; b[5] = b1.y; b[6] = b1.z; b[7] = b1.w;
#pragma unroll
            for (int i = 0; i < 4; i++)
#pragma unroll
                for (int j = 0; j < 8; j++) acc[i][j] += a[i] * b[j];
        }
        __syncthreads();
    }

#pragma unroll
    for (int i = 0; i < 4; i++) {
        const int n   = m0 + ty * 4 + i;
        const int t   = n / (H_ * W_);
        const int rem = n % (H_ * W_);
        const int col0 = tx * 8;
        const size_t o = (size_t)rem * (T_ * C_) + t * C_ + col0;
        *(float4*)&out[o]     = make_float4(acc[i][0], acc[i][1], acc[i][2], acc[i][3]);
        *(float4*)&out[o + 4] = make_float4(acc[i][4], acc[i][5], acc[i][6], acc[i][7]);
    }
}

// ---------------------------------------------------------------------------
extern "C" void kernel_launch(void* const* d_in, const int* in_sizes, int n_in,
                              void* d_out, int out_size)
{
    const float* x    = (const float*)d_in[0];
    const float* Wq   = (const float*)d_in[1];
    const float* Wk   = (const float*)d_in[2];
    const float* Wv   = (const float*)d_in[3];
    const float* Wo   = (const float*)d_in[4];
    const float* temp = (const float*)d_in[5];
    const float* sp   = (const float*)d_in[6];
    float* out = (float*)d_out;

    qkv_kernel<<<dim3(NT / 64, 3), 256>>>(x, Wq, Wk, Wv, temp, sp);

    const size_t smem = (size_t)(2 * TP * KPAD + T_ * CK + 24 * 76) * sizeof(float);
    cudaFuncSetAttribute(attn_kernel, cudaFuncAttributeMaxDynamicSharedMemorySize, (int)smem);
    attn_kernel<<<dim3(W_, H_), 768, smem>>>(sp);

    outproj_kernel<<<NT / 64, 256>>>(Wo, out);
}